// round 14
// baseline (speedup 1.0000x reference)
#include <cuda_runtime.h>
#include <cuda_fp16.h>
#include <math.h>

#define Dq   768
#define Gq   2048
#define Bq   128
#define NEGq 15
#define KC   64
#define NCHUNK 12
#define MAXROWS 36864

// Static scratch. Device symbols referenced ONLY from device code.
__device__ float g_part[(size_t)Gq * 96];
__device__ int   g_off[Gq];

__device__ __half g_xh[(size_t)MAXROWS * Dq];     // x fp16
__device__ __half g_xwh[(size_t)MAXROWS * Dq];    // xw fp16 (K1 output)
__device__ __half g_wh[(size_t)Dq * Dq];          // Wsfa fp16
__device__ __half g_w1h[(size_t)3072 * Dq];       // W1 fp16
__device__ __half g_ph[(size_t)Gq * Dq];          // pooled fp16 (K2 output)

// ---------------------------------------------------------------------------
// helpers (baseline sm_80 PTX only — harness compiles for plain sm_103)
// ---------------------------------------------------------------------------
__device__ __forceinline__ unsigned smem_u32(const void* p) {
    unsigned a;
    asm("{ .reg .u64 t; cvta.to.shared.u64 t, %1; cvt.u32.u64 %0, t; }"
        : "=r"(a) : "l"(p));
    return a;
}
__device__ __forceinline__ void cpa16(unsigned d, const void* s) {
    asm volatile("cp.async.cg.shared.global [%0], [%1], 16;" :: "r"(d), "l"(s));
}
__device__ __forceinline__ void ldm4(unsigned* r, unsigned a) {
    asm volatile("ldmatrix.sync.aligned.m8n8.x4.shared.b16 {%0,%1,%2,%3}, [%4];"
                 : "=r"(r[0]), "=r"(r[1]), "=r"(r[2]), "=r"(r[3]) : "r"(a));
}
__device__ __forceinline__ void mma16816(float* d, const unsigned* a,
                                         unsigned b0, unsigned b1) {
    asm volatile("mma.sync.aligned.m16n8k16.row.col.f32.f16.f16.f32 "
                 "{%0,%1,%2,%3}, {%4,%5,%6,%7}, {%8,%9}, {%0,%1,%2,%3};"
                 : "+f"(d[0]), "+f"(d[1]), "+f"(d[2]), "+f"(d[3])
                 : "r"(a[0]), "r"(a[1]), "r"(a[2]), "r"(a[3]), "r"(b0), "r"(b1));
}
// fp16-accumulator variant: D/C are 2 packed half2 regs.
// d[0] = row (lane>>2), cols 2(lane&3)+{0,1}; d[1] = row+8, same cols.
__device__ __forceinline__ void mma16816h(unsigned* d, const unsigned* a,
                                          unsigned b0, unsigned b1) {
    asm volatile("mma.sync.aligned.m16n8k16.row.col.f16.f16.f16.f16 "
                 "{%0,%1}, {%2,%3,%4,%5}, {%6,%7}, {%0,%1};"
                 : "+r"(d[0]), "+r"(d[1])
                 : "r"(a[0]), "r"(a[1]), "r"(a[2]), "r"(a[3]), "r"(b0), "r"(b1));
}

// ---------------------------------------------------------------------------
// fp32 -> fp16. DST 0: g_xh <- src ; 2: g_wh <- src ; 3: g_w1h <- src
// ---------------------------------------------------------------------------
template <int DST>
__global__ void kconv(const float* __restrict__ src, int n4)
{
    int i = blockIdx.x * blockDim.x + threadIdx.x;
    if (i >= n4) return;
    __half* hi = (DST == 0) ? g_xh : (DST == 2) ? g_wh : g_w1h;
    float4 v = ((const float4*)src)[i];
    float a[4] = {v.x, v.y, v.z, v.w};
    unsigned h[4];
#pragma unroll
    for (int j = 0; j < 4; j++)
        h[j] = (unsigned)__half_as_ushort(__float2half_rn(a[j]));
    ((uint2*)hi)[i] = make_uint2(h[0] | (h[1] << 16), h[2] | (h[3] << 16));
}

// ---------------------------------------------------------------------------
// GEMM via mma.sync fp16. CTA tile 128x128, K-chunk 64, 3-stage cp.async
// pipeline (one __syncthreads per chunk), pitch 144B, 2 CTAs/SM.
// FUSE=0: A=g_xh, B=g_wh, fp16 accumulate, C stored fp16 into g_xwh.
// FUSE=1: A=g_ph, B=g_w1h, fp32 accumulate, fused relu(D+b1).W2 -> g_part.
// ---------------------------------------------------------------------------
#define SPITCHB 144
#define TILEB   (128 * SPITCHB)
#define BUFB    (2 * TILEB)       // A tile + B tile
#define GSMEM   (3 * BUFB)        // 110592 B (3 pipeline stages)

template <int FUSE>
__global__ __launch_bounds__(256, 2) void gemm_mma(
    int M, const float* __restrict__ b1v, const float* __restrict__ w2v)
{
    const __half* __restrict__ Aa = FUSE ? g_ph  : g_xh;
    const __half* __restrict__ Bh = FUSE ? g_w1h : g_wh;

    extern __shared__ char smem[];
    unsigned sbase = smem_u32(smem);
    int tid = threadIdx.x, lane = tid & 31, wid = tid >> 5;
    int bm = blockIdx.y * 128, bn = blockIdx.x * 128;

    int sr = tid >> 1, sh = tid & 1;
    int arow = bm + sr; if (arow >= M) arow = M - 1;
    const __half* Asrc  = Aa + (size_t)arow * Dq + sh * 32;
    const __half* Bsrch = Bh + (size_t)(bn + sr) * Dq + sh * 32;
    unsigned sdst = sbase + sr * SPITCHB + sh * 64;

    float    accf[4][4][4];   // FUSE=1
    unsigned acch[4][4][2];   // FUSE=0 (packed half2 pairs)
#pragma unroll
    for (int i = 0; i < 4; i++)
#pragma unroll
        for (int j = 0; j < 4; j++) {
            if (FUSE) { accf[i][j][0] = accf[i][j][1] = accf[i][j][2] = accf[i][j][3] = 0.f; }
            else      { acch[i][j][0] = acch[i][j][1] = 0u; }
        }

    int wm = (wid >> 2) * 64;
    int wn = (wid & 3) * 32;
    unsigned a_base = sbase + (unsigned)(wm + (lane & 15)) * SPITCHB
                            + ((lane >> 4) << 4);
    unsigned bh_base = sbase + TILEB
        + (unsigned)(wn + (lane & 7) + ((lane >> 4) << 3)) * SPITCHB
        + (((lane >> 3) & 1) << 4);

    auto stage = [&](int c, int buf) {
        unsigned d = sdst + buf * BUFB;
        size_t off = (size_t)c * KC;
#pragma unroll
        for (int i = 0; i < 4; i++) {
            cpa16(d + i * 16,         Asrc  + off + i * 8);
            cpa16(d + TILEB + i * 16, Bsrch + off + i * 8);
        }
        asm volatile("cp.async.commit_group;" ::: "memory");
    };

    stage(0, 0);
    stage(1, 1);

    for (int c = 0; c < NCHUNK; c++) {
        if (c + 1 < NCHUNK)
            asm volatile("cp.async.wait_group 1;" ::: "memory");
        else
            asm volatile("cp.async.wait_group 0;" ::: "memory");
        __syncthreads();
        // stage(c+2) writes buf (c+2)%3 == (c-1)%3, whose readers finished
        // compute(c-1) before this barrier.
        if (c + 2 < NCHUNK) stage(c + 2, (c + 2) % 3);

        int buf = c % 3;
        unsigned ab = a_base  + buf * BUFB;
        unsigned hb = bh_base + buf * BUFB;
#pragma unroll
        for (int ks = 0; ks < 4; ks++) {
            unsigned af[4][4], bhf[2][4];
#pragma unroll
            for (int mt = 0; mt < 4; mt++)
                ldm4(af[mt], ab + mt * (16 * SPITCHB) + ks * 32);
#pragma unroll
            for (int np = 0; np < 2; np++)
                ldm4(bhf[np], hb + np * (16 * SPITCHB) + ks * 32);
#pragma unroll
            for (int mt = 0; mt < 4; mt++)
#pragma unroll
                for (int nt = 0; nt < 4; nt++) {
                    unsigned h0 = bhf[nt >> 1][(nt & 1) * 2];
                    unsigned h1 = bhf[nt >> 1][(nt & 1) * 2 + 1];
                    if (FUSE) mma16816(accf[mt][nt], af[mt], h0, h1);
                    else      mma16816h(acch[mt][nt], af[mt], h0, h1);
                }
        }
    }

    if (!FUSE) {
        // fp16 accumulators: packed half2 stores straight to g_xwh
#pragma unroll
        for (int mt = 0; mt < 4; mt++) {
            int r0 = bm + wm + mt * 16 + (lane >> 2);
#pragma unroll
            for (int nt = 0; nt < 4; nt++) {
                int col = bn + wn + nt * 8 + (lane & 3) * 2;
                if (r0 < M)
                    *(unsigned*)(g_xwh + (size_t)r0 * Dq + col) = acch[mt][nt][0];
                if (r0 + 8 < M)
                    *(unsigned*)(g_xwh + (size_t)(r0 + 8) * Dq + col) = acch[mt][nt][1];
            }
        }
    } else {
#pragma unroll
        for (int mt = 0; mt < 4; mt++) {
            float p0 = 0.f, p1 = 0.f;
#pragma unroll
            for (int nt = 0; nt < 4; nt++) {
                int col = bn + wn + nt * 8 + (lane & 3) * 2;
                float bb0 = b1v[col], bb1 = b1v[col + 1];
                float w0 = w2v[col],  w1 = w2v[col + 1];
                p0 = fmaf(fmaxf(accf[mt][nt][0] + bb0, 0.f), w0, p0);
                p0 = fmaf(fmaxf(accf[mt][nt][1] + bb1, 0.f), w1, p0);
                p1 = fmaf(fmaxf(accf[mt][nt][2] + bb0, 0.f), w0, p1);
                p1 = fmaf(fmaxf(accf[mt][nt][3] + bb1, 0.f), w1, p1);
            }
            p0 += __shfl_xor_sync(0xffffffffu, p0, 1);
            p0 += __shfl_xor_sync(0xffffffffu, p0, 2);
            p1 += __shfl_xor_sync(0xffffffffu, p1, 1);
            p1 += __shfl_xor_sync(0xffffffffu, p1, 2);
            if ((lane & 3) == 0) {
                int r0 = bm + wm + mt * 16 + (lane >> 2);
                int pc = blockIdx.x * 4 + (wid & 3);
                g_part[(size_t)r0 * 96 + pc] = p0;
                g_part[(size_t)(r0 + 8) * 96 + pc] = p1;
            }
        }
    }
}

// ---------------------------------------------------------------------------
// K0: offsets (prefix sum of 2048 sizes)
// ---------------------------------------------------------------------------
__global__ void k0_offsets(const int* __restrict__ sizes) {
    __shared__ int part[256];
    __shared__ int base[256];
    int tid = threadIdx.x;
    int loc[8];
    int ssum = 0;
#pragma unroll
    for (int i = 0; i < 8; i++) { loc[i] = ssum; ssum += sizes[tid * 8 + i]; }
    part[tid] = ssum;
    __syncthreads();
    if (tid == 0) {
        int run = 0;
        for (int i = 0; i < 256; i++) { int v = part[i]; base[i] = run; run += v; }
    }
    __syncthreads();
    int b0 = base[tid];
#pragma unroll
    for (int i = 0; i < 8; i++) g_off[tid * 8 + i] = b0 + loc[i];
}

// ---------------------------------------------------------------------------
// K2: per-group attention + pooling, tensor-core S product (as in R11).
// ---------------------------------------------------------------------------
#define P2      1552
#define K2_XOFF 0
#define K2_WOFF (32 * P2)
#define K2_ROFF (2 * 32 * P2)
#define K2_RPW  (32 * 34)
#define K2_SOFF (K2_ROFF + 8 * K2_RPW * 4)
#define K2_AOFF (K2_SOFF + 32 * 33 * 4)
#define K2SMEM  (K2_AOFF + 128)

__global__ __launch_bounds__(256) void k2_attention(const int* __restrict__ sizes)
{
    extern __shared__ char smem[];
    unsigned sbase = smem_u32(smem);
    float* S   = (float*)(smem + K2_SOFF);
    float* att = (float*)(smem + K2_AOFF);
    float* red = (float*)(smem + K2_ROFF);

    int g = blockIdx.x;
    int s = sizes[g];
    int base = g_off[g];
    int tid = threadIdx.x, lane = tid & 31, wid = tid >> 5;

    const uint4* xs4 = (const uint4*)(g_xh  + (size_t)base * Dq);
    const uint4* ws4 = (const uint4*)(g_xwh + (size_t)base * Dq);
    int tot16 = s * 96;
    for (int i = tid; i < tot16; i += 256) {
        int row = i / 96, c = i - row * 96;
        *(uint4*)(smem + K2_XOFF + row * P2 + c * 16) = xs4[i];
        *(uint4*)(smem + K2_WOFF + row * P2 + c * 16) = ws4[i];
    }
    __syncthreads();

    {
        unsigned a_base = sbase + K2_XOFF + (unsigned)(lane & 15) * P2
                        + ((lane >> 4) << 4);
        unsigned b_base = sbase + K2_WOFF
                        + (unsigned)((lane & 7) + ((lane >> 4) << 3)) * P2
                        + (((lane >> 3) & 1) << 4);
        float c[2][4][4];
#pragma unroll
        for (int i = 0; i < 2; i++)
#pragma unroll
            for (int j = 0; j < 4; j++)
#pragma unroll
                for (int k = 0; k < 4; k++) c[i][j][k] = 0.f;
        unsigned wko = (unsigned)(wid * 192);
#pragma unroll
        for (int ks = 0; ks < 6; ks++) {
            unsigned koff = wko + ks * 32;
            unsigned af[2][4], bf[2][4];
            ldm4(af[0], a_base + koff);
            ldm4(af[1], a_base + 16 * P2 + koff);
            ldm4(bf[0], b_base + koff);
            ldm4(bf[1], b_base + 16 * P2 + koff);
#pragma unroll
            for (int mt = 0; mt < 2; mt++)
#pragma unroll
                for (int nt = 0; nt < 4; nt++)
                    mma16816(c[mt][nt], af[mt],
                             bf[nt >> 1][(nt & 1) * 2],
                             bf[nt >> 1][(nt & 1) * 2 + 1]);
        }
        float* rw = red + wid * K2_RPW;
#pragma unroll
        for (int mt = 0; mt < 2; mt++)
#pragma unroll
            for (int nt = 0; nt < 4; nt++) {
                int row = mt * 16 + (lane >> 2);
                int col = nt * 8 + (lane & 3) * 2;
                *(float2*)&rw[row * 34 + col] =
                    make_float2(c[mt][nt][0], c[mt][nt][1]);
                *(float2*)&rw[(row + 8) * 34 + col] =
                    make_float2(c[mt][nt][2], c[mt][nt][3]);
            }
    }
    __syncthreads();

    {
        int e0 = tid * 4;
        int row = e0 >> 5, col = e0 & 31;
#pragma unroll
        for (int j = 0; j < 4; j++) {
            float v = 0.f;
#pragma unroll
            for (int w = 0; w < 8; w++)
                v += red[w * K2_RPW + row * 34 + col + j];
            if (row < s && col + j < s) S[row * 33 + col + j] = tanhf(v);
        }
    }
    __syncthreads();

    if (tid < 32) {
        int m = tid;
        float mx = -INFINITY;
        if (m < s)
            for (int l = 0; l < s; l++) mx = fmaxf(mx, S[l * 33 + m]);
        float wm = mx;
#pragma unroll
        for (int o = 16; o > 0; o >>= 1) wm = fmaxf(wm, __shfl_xor_sync(0xffffffffu, wm, o));
        float e = (m < s) ? expf(mx - wm) : 0.f;
        float se = e;
#pragma unroll
        for (int o = 16; o > 0; o >>= 1) se += __shfl_xor_sync(0xffffffffu, se, o);
        att[m] = e / se;
    }
    __syncthreads();

    __half* outp = g_ph + (size_t)g * Dq;
    for (int d = tid; d < Dq; d += 256) {
        float a = 0.f;
        for (int m = 0; m < s; m++) {
            __half xv = *(const __half*)(smem + K2_XOFF + m * P2 + d * 2);
            a = fmaf(att[m], __half2float(xv), a);
        }
        outp[d] = __float2half_rn(a);
    }
}

// ---------------------------------------------------------------------------
// K4: scores = sigmoid(sum of 96 partials + b2); margin-ranking loss.
// ---------------------------------------------------------------------------
__global__ void k4_loss(const float* __restrict__ b2, float* __restrict__ out) {
    __shared__ float sc[Gq];
    __shared__ float red[256];
    int tid = threadIdx.x;
    float bb = b2[0];
    for (int gi = tid; gi < Gq; gi += 256) {
        const float* pp = g_part + (size_t)gi * 96;
        float a = 0.f;
#pragma unroll
        for (int c = 0; c < 96; c++) a += pp[c];
        sc[gi] = 1.f / (1.f + expf(-(a + bb)));
    }
    __syncthreads();
    float s = 0.f;
    for (int idx = tid; idx < Bq * NEGq; idx += 256) {
        int b = idx / NEGq;
        int j = idx % NEGq + 1;
        float v = sc[b * 16 + j] + 0.1f - sc[b * 16];
        s += fmaxf(v, 0.f);
    }
    red[tid] = s;
    __syncthreads();
    for (int o = 128; o > 0; o >>= 1) {
        if (tid < o) red[tid] += red[tid + o];
        __syncthreads();
    }
    if (tid == 0) out[0] = red[0];
}

// ---------------------------------------------------------------------------
extern "C" void kernel_launch(void* const* d_in, const int* in_sizes, int n_in,
                              void* d_out, int out_size) {
    const float* x    = (const float*)d_in[0];
    const float* Wsfa = (const float*)d_in[1];
    const float* W1   = (const float*)d_in[2];
    const float* b1   = (const float*)d_in[3];
    const float* W2   = (const float*)d_in[4];
    const float* b2   = (const float*)d_in[5];
    const int* sizes  = (const int*)d_in[6];
    float* out = (float*)d_out;
    int N = in_sizes[0] / Dq;

    cudaFuncSetAttribute(gemm_mma<0>, cudaFuncAttributeMaxDynamicSharedMemorySize, GSMEM);
    cudaFuncSetAttribute(gemm_mma<1>, cudaFuncAttributeMaxDynamicSharedMemorySize, GSMEM);
    cudaFuncSetAttribute(k2_attention, cudaFuncAttributeMaxDynamicSharedMemorySize, K2SMEM);

    k0_offsets<<<1, 256>>>(sizes);

    int n4x = N * Dq / 4;
    kconv<0><<<(n4x + 255) / 256, 256>>>(x, n4x);
    kconv<2><<<(Dq * Dq / 4 + 255) / 256, 256>>>(Wsfa, Dq * Dq / 4);
    kconv<3><<<(3072 * Dq / 4 + 255) / 256, 256>>>(W1, 3072 * Dq / 4);

    dim3 g1(Dq / 128, (N + 127) / 128);
    gemm_mma<0><<<g1, 256, GSMEM>>>(N, nullptr, nullptr);

    k2_attention<<<Gq, 256, K2SMEM>>>(sizes);

    dim3 g3(3072 / 128, Gq / 128);
    gemm_mma<1><<<g3, 256, GSMEM>>>(Gq, b1, W2);

    k4_loss<<<1, 256>>>(b2, out);
}

// round 17
// speedup vs baseline: 1.0377x; 1.0377x over previous
#include <cuda_runtime.h>
#include <cuda_fp16.h>
#include <math.h>

#define Dq   768
#define Gq   2048
#define Bq   128
#define NEGq 15
#define KC   64
#define NCHUNK 12
#define MAXROWS 36864

// Static scratch. Device symbols referenced ONLY from device code.
__device__ float g_part[(size_t)Gq * 96];
__device__ int   g_off[Gq];

__device__ __half g_xh[(size_t)MAXROWS * Dq];     // x fp16
__device__ __half g_xwh[(size_t)MAXROWS * Dq];    // xw fp16 (K1 output)
__device__ __half g_wh[(size_t)Dq * Dq];          // Wsfa fp16
__device__ __half g_w1h[(size_t)3072 * Dq];       // W1 fp16
__device__ __half g_ph[(size_t)Gq * Dq];          // pooled fp16 (K2 output)

// ---------------------------------------------------------------------------
// helpers (baseline sm_80 PTX only — harness compiles for plain sm_103)
// ---------------------------------------------------------------------------
__device__ __forceinline__ unsigned smem_u32(const void* p) {
    unsigned a;
    asm("{ .reg .u64 t; cvta.to.shared.u64 t, %1; cvt.u32.u64 %0, t; }"
        : "=r"(a) : "l"(p));
    return a;
}
__device__ __forceinline__ void cpa16(unsigned d, const void* s) {
    asm volatile("cp.async.cg.shared.global [%0], [%1], 16;" :: "r"(d), "l"(s));
}
__device__ __forceinline__ void ldm4(unsigned* r, unsigned a) {
    asm volatile("ldmatrix.sync.aligned.m8n8.x4.shared.b16 {%0,%1,%2,%3}, [%4];"
                 : "=r"(r[0]), "=r"(r[1]), "=r"(r[2]), "=r"(r[3]) : "r"(a));
}
__device__ __forceinline__ void mma16816(float* d, const unsigned* a,
                                         unsigned b0, unsigned b1) {
    asm volatile("mma.sync.aligned.m16n8k16.row.col.f32.f16.f16.f32 "
                 "{%0,%1,%2,%3}, {%4,%5,%6,%7}, {%8,%9}, {%0,%1,%2,%3};"
                 : "+f"(d[0]), "+f"(d[1]), "+f"(d[2]), "+f"(d[3])
                 : "r"(a[0]), "r"(a[1]), "r"(a[2]), "r"(a[3]), "r"(b0), "r"(b1));
}
// fp16-accumulator variant: d[0] = row (lane>>2), d[1] = row+8.
__device__ __forceinline__ void mma16816h(unsigned* d, const unsigned* a,
                                          unsigned b0, unsigned b1) {
    asm volatile("mma.sync.aligned.m16n8k16.row.col.f16.f16.f16.f16 "
                 "{%0,%1}, {%2,%3,%4,%5}, {%6,%7}, {%0,%1};"
                 : "+r"(d[0]), "+r"(d[1])
                 : "r"(a[0]), "r"(a[1]), "r"(a[2]), "r"(a[3]), "r"(b0), "r"(b1));
}

// ---------------------------------------------------------------------------
// fp32 -> fp16. DST 0: g_xh <- src ; 2: g_wh <- src ; 3: g_w1h <- src
// ---------------------------------------------------------------------------
template <int DST>
__global__ void kconv(const float* __restrict__ src, int n4)
{
    int i = blockIdx.x * blockDim.x + threadIdx.x;
    if (i >= n4) return;
    __half* hi = (DST == 0) ? g_xh : (DST == 2) ? g_wh : g_w1h;
    float4 v = ((const float4*)src)[i];
    float a[4] = {v.x, v.y, v.z, v.w};
    unsigned h[4];
#pragma unroll
    for (int j = 0; j < 4; j++)
        h[j] = (unsigned)__half_as_ushort(__float2half_rn(a[j]));
    ((uint2*)hi)[i] = make_uint2(h[0] | (h[1] << 16), h[2] | (h[3] << 16));
}

#define SPITCHB 144

// ---------------------------------------------------------------------------
// K1: xw = x @ Wsfa^T, fp16 in/out, fp16 accumulate.
// CTA tile 128x256 (M x N), 8 warps of 64x64 -> 8 ldm4 per 32 MMAs.
// 2-stage cp.async pipeline (R11 scheme), pitch 144B, 2 CTAs/SM.
// ---------------------------------------------------------------------------
#define K1_AT   (128 * SPITCHB)            // 18432
#define K1_BT   (256 * SPITCHB)            // 36864
#define K1_BUF  (K1_AT + K1_BT)            // 55296
#define K1_SMEM (2 * K1_BUF)               // 110592

__global__ __launch_bounds__(256, 2) void gemm_k1(int M)
{
    extern __shared__ char smem[];
    unsigned sbase = smem_u32(smem);
    int tid = threadIdx.x, lane = tid & 31, wid = tid >> 5;
    int bm = blockIdx.y * 128, bn = blockIdx.x * 256;

    int sr = tid >> 1, sh = tid & 1;
    int arow = bm + sr; if (arow >= M) arow = M - 1;
    const __half* Asrc = g_xh + (size_t)arow * Dq + sh * 32;
    const __half* Bs0  = g_wh + (size_t)(bn + sr) * Dq + sh * 32;
    const __half* Bs1  = g_wh + (size_t)(bn + sr + 128) * Dq + sh * 32;
    unsigned dA  = sbase + sr * SPITCHB + sh * 64;
    unsigned dB0 = sbase + K1_AT + sr * SPITCHB + sh * 64;
    unsigned dB1 = sbase + K1_AT + (sr + 128) * SPITCHB + sh * 64;

    unsigned acch[4][8][2];
#pragma unroll
    for (int i = 0; i < 4; i++)
#pragma unroll
        for (int j = 0; j < 8; j++) { acch[i][j][0] = 0u; acch[i][j][1] = 0u; }

    int wm = (wid >> 2) * 64;          // 0 | 64
    int wn = (wid & 3) * 64;           // 0..192
    unsigned a_base = sbase + (unsigned)(wm + (lane & 15)) * SPITCHB
                            + ((lane >> 4) << 4);
    unsigned b_base = sbase + K1_AT
        + (unsigned)(wn + (lane & 7) + ((lane >> 4) << 3)) * SPITCHB
        + (((lane >> 3) & 1) << 4);

    auto stage = [&](int c, int buf) {
        unsigned o = buf * K1_BUF;
        size_t off = (size_t)c * KC;
#pragma unroll
        for (int i = 0; i < 4; i++) {
            cpa16(dA  + o + i * 16, Asrc + off + i * 8);
            cpa16(dB0 + o + i * 16, Bs0  + off + i * 8);
            cpa16(dB1 + o + i * 16, Bs1  + off + i * 8);
        }
        asm volatile("cp.async.commit_group;" ::: "memory");
    };

    stage(0, 0);
    asm volatile("cp.async.wait_group 0;" ::: "memory");
    __syncthreads();

    for (int c = 0; c < NCHUNK; c++) {
        if (c + 1 < NCHUNK) stage(c + 1, (c + 1) & 1);
        unsigned ab = a_base + (c & 1) * K1_BUF;
        unsigned bb = b_base + (c & 1) * K1_BUF;
#pragma unroll
        for (int ks = 0; ks < 4; ks++) {
            unsigned af[4][4], bf[4][4];
#pragma unroll
            for (int mt = 0; mt < 4; mt++)
                ldm4(af[mt], ab + mt * (16 * SPITCHB) + ks * 32);
#pragma unroll
            for (int np = 0; np < 4; np++)
                ldm4(bf[np], bb + np * (16 * SPITCHB) + ks * 32);
#pragma unroll
            for (int mt = 0; mt < 4; mt++)
#pragma unroll
                for (int nt = 0; nt < 8; nt++)
                    mma16816h(acch[mt][nt], af[mt],
                              bf[nt >> 1][(nt & 1) * 2],
                              bf[nt >> 1][(nt & 1) * 2 + 1]);
        }
        if (c + 1 < NCHUNK) {
            asm volatile("cp.async.wait_group 0;" ::: "memory");
            __syncthreads();
        }
    }

#pragma unroll
    for (int mt = 0; mt < 4; mt++) {
        int r0 = bm + wm + mt * 16 + (lane >> 2);
#pragma unroll
        for (int nt = 0; nt < 8; nt++) {
            int col = bn + wn + nt * 8 + (lane & 3) * 2;
            if (r0 < M)
                *(unsigned*)(g_xwh + (size_t)r0 * Dq + col) = acch[mt][nt][0];
            if (r0 + 8 < M)
                *(unsigned*)(g_xwh + (size_t)(r0 + 8) * Dq + col) = acch[mt][nt][1];
        }
    }
}

// ---------------------------------------------------------------------------
// K3: fused MLP GEMM (exact R11 FUSE=1 config: 128x128, warp 64x32, f32 acc,
// 2-stage pipeline). A=g_ph, B=g_w1h, epilogue relu(D+b1).W2 -> g_part.
// ---------------------------------------------------------------------------
#define TILEB   (128 * SPITCHB)
#define K3_BUF  (2 * TILEB)
#define K3_SMEM (2 * K3_BUF)               // 73728

__global__ __launch_bounds__(256, 2) void gemm_k3(
    int M, const float* __restrict__ b1v, const float* __restrict__ w2v)
{
    extern __shared__ char smem[];
    unsigned sbase = smem_u32(smem);
    int tid = threadIdx.x, lane = tid & 31, wid = tid >> 5;
    int bm = blockIdx.y * 128, bn = blockIdx.x * 128;

    int sr = tid >> 1, sh = tid & 1;
    int arow = bm + sr; if (arow >= M) arow = M - 1;
    const __half* Asrc  = g_ph  + (size_t)arow * Dq + sh * 32;
    const __half* Bsrch = g_w1h + (size_t)(bn + sr) * Dq + sh * 32;
    unsigned sdst = sbase + sr * SPITCHB + sh * 64;

    float acc[4][4][4];
#pragma unroll
    for (int i = 0; i < 4; i++)
#pragma unroll
        for (int j = 0; j < 4; j++)
#pragma unroll
            for (int k = 0; k < 4; k++) acc[i][j][k] = 0.f;

    int wm = (wid >> 2) * 64;
    int wn = (wid & 3) * 32;
    unsigned a_base = sbase + (unsigned)(wm + (lane & 15)) * SPITCHB
                            + ((lane >> 4) << 4);
    unsigned bh_base = sbase + TILEB
        + (unsigned)(wn + (lane & 7) + ((lane >> 4) << 3)) * SPITCHB
        + (((lane >> 3) & 1) << 4);

    auto stage = [&](int c, int buf) {
        unsigned d = sdst + buf * K3_BUF;
        size_t off = (size_t)c * KC;
#pragma unroll
        for (int i = 0; i < 4; i++) {
            cpa16(d + i * 16,         Asrc  + off + i * 8);
            cpa16(d + TILEB + i * 16, Bsrch + off + i * 8);
        }
        asm volatile("cp.async.commit_group;" ::: "memory");
    };

    stage(0, 0);
    asm volatile("cp.async.wait_group 0;" ::: "memory");
    __syncthreads();

    for (int c = 0; c < NCHUNK; c++) {
        if (c + 1 < NCHUNK) stage(c + 1, (c + 1) & 1);
        unsigned ab = a_base  + (c & 1) * K3_BUF;
        unsigned hb = bh_base + (c & 1) * K3_BUF;
#pragma unroll
        for (int ks = 0; ks < 4; ks++) {
            unsigned af[4][4], bhf[2][4];
#pragma unroll
            for (int mt = 0; mt < 4; mt++)
                ldm4(af[mt], ab + mt * (16 * SPITCHB) + ks * 32);
#pragma unroll
            for (int np = 0; np < 2; np++)
                ldm4(bhf[np], hb + np * (16 * SPITCHB) + ks * 32);
#pragma unroll
            for (int mt = 0; mt < 4; mt++)
#pragma unroll
                for (int nt = 0; nt < 4; nt++)
                    mma16816(acc[mt][nt], af[mt],
                             bhf[nt >> 1][(nt & 1) * 2],
                             bhf[nt >> 1][(nt & 1) * 2 + 1]);
        }
        if (c + 1 < NCHUNK) {
            asm volatile("cp.async.wait_group 0;" ::: "memory");
            __syncthreads();
        }
    }

#pragma unroll
    for (int mt = 0; mt < 4; mt++) {
        float p0 = 0.f, p1 = 0.f;
#pragma unroll
        for (int nt = 0; nt < 4; nt++) {
            int col = bn + wn + nt * 8 + (lane & 3) * 2;
            float bb0 = b1v[col], bb1 = b1v[col + 1];
            float w0 = w2v[col],  w1 = w2v[col + 1];
            p0 = fmaf(fmaxf(acc[mt][nt][0] + bb0, 0.f), w0, p0);
            p0 = fmaf(fmaxf(acc[mt][nt][1] + bb1, 0.f), w1, p0);
            p1 = fmaf(fmaxf(acc[mt][nt][2] + bb0, 0.f), w0, p1);
            p1 = fmaf(fmaxf(acc[mt][nt][3] + bb1, 0.f), w1, p1);
        }
        p0 += __shfl_xor_sync(0xffffffffu, p0, 1);
        p0 += __shfl_xor_sync(0xffffffffu, p0, 2);
        p1 += __shfl_xor_sync(0xffffffffu, p1, 1);
        p1 += __shfl_xor_sync(0xffffffffu, p1, 2);
        if ((lane & 3) == 0) {
            int r0 = bm + wm + mt * 16 + (lane >> 2);
            int pc = blockIdx.x * 4 + (wid & 3);
            g_part[(size_t)r0 * 96 + pc] = p0;
            g_part[(size_t)(r0 + 8) * 96 + pc] = p1;
        }
    }
}

// ---------------------------------------------------------------------------
// K0: offsets (prefix sum of 2048 sizes)
// ---------------------------------------------------------------------------
__global__ void k0_offsets(const int* __restrict__ sizes) {
    __shared__ int part[256];
    __shared__ int base[256];
    int tid = threadIdx.x;
    int loc[8];
    int ssum = 0;
#pragma unroll
    for (int i = 0; i < 8; i++) { loc[i] = ssum; ssum += sizes[tid * 8 + i]; }
    part[tid] = ssum;
    __syncthreads();
    if (tid == 0) {
        int run = 0;
        for (int i = 0; i < 256; i++) { int v = part[i]; base[i] = run; run += v; }
    }
    __syncthreads();
    int b0 = base[tid];
#pragma unroll
    for (int i = 0; i < 8; i++) g_off[tid * 8 + i] = b0 + loc[i];
}

// ---------------------------------------------------------------------------
// K2: per-group attention + pooling, tensor-core S product (as in R11).
// ---------------------------------------------------------------------------
#define P2      1552
#define K2_XOFF 0
#define K2_WOFF (32 * P2)
#define K2_ROFF (2 * 32 * P2)
#define K2_RPW  (32 * 34)
#define K2_SOFF (K2_ROFF + 8 * K2_RPW * 4)
#define K2_AOFF (K2_SOFF + 32 * 33 * 4)
#define K2SMEM  (K2_AOFF + 128)

__global__ __launch_bounds__(256) void k2_attention(const int* __restrict__ sizes)
{
    extern __shared__ char smem[];
    unsigned sbase = smem_u32(smem);
    float* S   = (float*)(smem + K2_SOFF);
    float* att = (float*)(smem + K2_AOFF);
    float* red = (float*)(smem + K2_ROFF);

    int g = blockIdx.x;
    int s = sizes[g];
    int base = g_off[g];
    int tid = threadIdx.x, lane = tid & 31, wid = tid >> 5;

    const uint4* xs4 = (const uint4*)(g_xh  + (size_t)base * Dq);
    const uint4* ws4 = (const uint4*)(g_xwh + (size_t)base * Dq);
    int tot16 = s * 96;
    for (int i = tid; i < tot16; i += 256) {
        int row = i / 96, c = i - row * 96;
        *(uint4*)(smem + K2_XOFF + row * P2 + c * 16) = xs4[i];
        *(uint4*)(smem + K2_WOFF + row * P2 + c * 16) = ws4[i];
    }
    __syncthreads();

    {
        unsigned a_base = sbase + K2_XOFF + (unsigned)(lane & 15) * P2
                        + ((lane >> 4) << 4);
        unsigned b_base = sbase + K2_WOFF
                        + (unsigned)((lane & 7) + ((lane >> 4) << 3)) * P2
                        + (((lane >> 3) & 1) << 4);
        float c[2][4][4];
#pragma unroll
        for (int i = 0; i < 2; i++)
#pragma unroll
            for (int j = 0; j < 4; j++)
#pragma unroll
                for (int k = 0; k < 4; k++) c[i][j][k] = 0.f;
        unsigned wko = (unsigned)(wid * 192);
#pragma unroll
        for (int ks = 0; ks < 6; ks++) {
            unsigned koff = wko + ks * 32;
            unsigned af[2][4], bf[2][4];
            ldm4(af[0], a_base + koff);
            ldm4(af[1], a_base + 16 * P2 + koff);
            ldm4(bf[0], b_base + koff);
            ldm4(bf[1], b_base + 16 * P2 + koff);
#pragma unroll
            for (int mt = 0; mt < 2; mt++)
#pragma unroll
                for (int nt = 0; nt < 4; nt++)
                    mma16816(c[mt][nt], af[mt],
                             bf[nt >> 1][(nt & 1) * 2],
                             bf[nt >> 1][(nt & 1) * 2 + 1]);
        }
        float* rw = red + wid * K2_RPW;
#pragma unroll
        for (int mt = 0; mt < 2; mt++)
#pragma unroll
            for (int nt = 0; nt < 4; nt++) {
                int row = mt * 16 + (lane >> 2);
                int col = nt * 8 + (lane & 3) * 2;
                *(float2*)&rw[row * 34 + col] =
                    make_float2(c[mt][nt][0], c[mt][nt][1]);
                *(float2*)&rw[(row + 8) * 34 + col] =
                    make_float2(c[mt][nt][2], c[mt][nt][3]);
            }
    }
    __syncthreads();

    {
        int e0 = tid * 4;
        int row = e0 >> 5, col = e0 & 31;
#pragma unroll
        for (int j = 0; j < 4; j++) {
            float v = 0.f;
#pragma unroll
            for (int w = 0; w < 8; w++)
                v += red[w * K2_RPW + row * 34 + col + j];
            if (row < s && col + j < s) S[row * 33 + col + j] = tanhf(v);
        }
    }
    __syncthreads();

    if (tid < 32) {
        int m = tid;
        float mx = -INFINITY;
        if (m < s)
            for (int l = 0; l < s; l++) mx = fmaxf(mx, S[l * 33 + m]);
        float wm = mx;
#pragma unroll
        for (int o = 16; o > 0; o >>= 1) wm = fmaxf(wm, __shfl_xor_sync(0xffffffffu, wm, o));
        float e = (m < s) ? expf(mx - wm) : 0.f;
        float se = e;
#pragma unroll
        for (int o = 16; o > 0; o >>= 1) se += __shfl_xor_sync(0xffffffffu, se, o);
        att[m] = e / se;
    }
    __syncthreads();

    __half* outp = g_ph + (size_t)g * Dq;
    for (int d = tid; d < Dq; d += 256) {
        float a = 0.f;
        for (int m = 0; m < s; m++) {
            __half xv = *(const __half*)(smem + K2_XOFF + m * P2 + d * 2);
            a = fmaf(att[m], __half2float(xv), a);
        }
        outp[d] = __float2half_rn(a);
    }
}

// ---------------------------------------------------------------------------
// K4: scores = sigmoid(sum of 96 partials + b2); margin-ranking loss.
// ---------------------------------------------------------------------------
__global__ void k4_loss(const float* __restrict__ b2, float* __restrict__ out) {
    __shared__ float sc[Gq];
    __shared__ float red[256];
    int tid = threadIdx.x;
    float bb = b2[0];
    for (int gi = tid; gi < Gq; gi += 256) {
        const float* pp = g_part + (size_t)gi * 96;
        float a = 0.f;
#pragma unroll
        for (int c = 0; c < 96; c++) a += pp[c];
        sc[gi] = 1.f / (1.f + expf(-(a + bb)));
    }
    __syncthreads();
    float s = 0.f;
    for (int idx = tid; idx < Bq * NEGq; idx += 256) {
        int b = idx / NEGq;
        int j = idx % NEGq + 1;
        float v = sc[b * 16 + j] + 0.1f - sc[b * 16];
        s += fmaxf(v, 0.f);
    }
    red[tid] = s;
    __syncthreads();
    for (int o = 128; o > 0; o >>= 1) {
        if (tid < o) red[tid] += red[tid + o];
        __syncthreads();
    }
    if (tid == 0) out[0] = red[0];
}

// ---------------------------------------------------------------------------
extern "C" void kernel_launch(void* const* d_in, const int* in_sizes, int n_in,
                              void* d_out, int out_size) {
    const float* x    = (const float*)d_in[0];
    const float* Wsfa = (const float*)d_in[1];
    const float* W1   = (const float*)d_in[2];
    const float* b1   = (const float*)d_in[3];
    const float* W2   = (const float*)d_in[4];
    const float* b2   = (const float*)d_in[5];
    const int* sizes  = (const int*)d_in[6];
    float* out = (float*)d_out;
    int N = in_sizes[0] / Dq;

    cudaFuncSetAttribute(gemm_k1, cudaFuncAttributeMaxDynamicSharedMemorySize, K1_SMEM);
    cudaFuncSetAttribute(gemm_k3, cudaFuncAttributeMaxDynamicSharedMemorySize, K3_SMEM);
    cudaFuncSetAttribute(k2_attention, cudaFuncAttributeMaxDynamicSharedMemorySize, K2SMEM);

    k0_offsets<<<1, 256>>>(sizes);

    int n4x = N * Dq / 4;
    kconv<0><<<(n4x + 255) / 256, 256>>>(x, n4x);
    kconv<2><<<(Dq * Dq / 4 + 255) / 256, 256>>>(Wsfa, Dq * Dq / 4);
    kconv<3><<<(3072 * Dq / 4 + 255) / 256, 256>>>(W1, 3072 * Dq / 4);

    dim3 g1(Dq / 256, (N + 127) / 128);      // (3, 264)
    gemm_k1<<<g1, 256, K1_SMEM>>>(N);

    k2_attention<<<Gq, 256, K2SMEM>>>(sizes);

    dim3 g3(3072 / 128, Gq / 128);           // (24, 16)
    gemm_k3<<<g3, 256, K3_SMEM>>>(Gq, b1, W2);

    k4_loss<<<1, 256>>>(b2, out);
}